// round 15
// baseline (speedup 1.0000x reference)
#include <cuda_runtime.h>
#include <cuda_fp16.h>
#include <cstdint>

// Problem constants (B=4, S=2048, D=1024, E=8, F=2048, top_k=2)
#define T_TOK 8192
#define D_DIM 1024
#define E_NUM 8
#define F_DIM 2048
#define RMAX  (2 * T_TOK)

#define BM 128
#define BN 128
#define BK 64                         // 64 fp16 k-values = 128B rows
#define STAGE_BYTES (2 * 16384)       // A | B, 16KB each
#define SMEM_SZ (1024 + 2 * STAGE_BYTES)   // 2-stage -> 65KB, 2 CTAs/SM

#define NSM 148
#define GEMM_CTAS (2 * NSM)           // persistent grid
#define MAX_TILES 192                 // >= sum_e ceil(n_e/BM) (<=136)

// ---------------- device scratch (no allocation allowed) --------------------
__device__ __half g_x16[(size_t)T_TOK * D_DIM];                // x fp16
__device__ __half g_H16[(size_t)RMAX * F_DIM];                 // H fp16
__device__ __half g_Y16[(size_t)RMAX * D_DIM];                 // expert outputs fp16
__device__ __half g_w1t[(size_t)E_NUM * F_DIM * D_DIM];        // [E][F][D] fp16
__device__ __half g_w2t[(size_t)E_NUM * D_DIM * F_DIM];        // [E][D][F] fp16
__device__ int   g_rows_token[RMAX];
__device__ int   g_tok2row[2 * T_TOK];
__device__ int   g_top_i[2 * T_TOK];
__device__ float g_top_w[2 * T_TOK];
__device__ int   g_counts[E_NUM];
__device__ int   g_offsets[E_NUM];
__device__ int   g_cursor[E_NUM];
__device__ int   g_tiles[MAX_TILES];   // packed e<<16 | (row0>>7)
__device__ int   g_ntiles;
__device__ int   g_ticket[2];          // work tickets for gemm1 / gemm2

// ---------------- helpers ----------------------------------------------------
__device__ __forceinline__ uint32_t smem_u32(const void* p) {
    uint32_t a;
    asm("{ .reg .u64 t; cvta.to.shared.u64 t, %1; cvt.u32.u64 %0, t; }"
        : "=r"(a) : "l"(p));
    return a;
}
// standard 128B-row swizzle (Swizzle<3,4,3>): 16B-col bits[6:4] ^= row bits[9:7]
#define SWZ128(o) ((o) ^ (((o) >> 3) & 0x70))

__device__ __forceinline__ void ldsm4(uint32_t* r, uint32_t addr) {
    asm volatile("ldmatrix.sync.aligned.m8n8.x4.shared.b16 {%0,%1,%2,%3}, [%4];"
                 : "=r"(r[0]), "=r"(r[1]), "=r"(r[2]), "=r"(r[3]) : "r"(addr));
}
__device__ __forceinline__ void hmma(float* c, const uint32_t* a,
                                     const uint32_t* b) {
    asm volatile(
        "mma.sync.aligned.m16n8k16.row.col.f32.f16.f16.f32 "
        "{%0,%1,%2,%3}, {%4,%5,%6,%7}, {%8,%9}, {%0,%1,%2,%3};"
        : "+f"(c[0]), "+f"(c[1]), "+f"(c[2]), "+f"(c[3])
        : "r"(a[0]), "r"(a[1]), "r"(a[2]), "r"(a[3]), "r"(b[0]), "r"(b[1]));
}
__device__ __forceinline__ void cp16(uint32_t dst, const void* src, int nbytes) {
    asm volatile("cp.async.cg.shared.global [%0], [%1], 16, %2;"
                 :: "r"(dst), "l"(src), "r"(nbytes) : "memory");
}
__device__ __forceinline__ void cp_commit() {
    asm volatile("cp.async.commit_group;" ::: "memory");
}
__device__ __forceinline__ void cp_wait1() {
    asm volatile("cp.async.wait_group 1;" ::: "memory");
}

// ---------------- init ------------------------------------------------------
__global__ void init_kernel() {
    int i = threadIdx.x;
    if (i < E_NUM) { g_counts[i] = 0; g_cursor[i] = 0; }
    if (i < 2) g_ticket[i] = 0;
}

// ---------------- router (+ fused x -> fp16 emit) ----------------------------
__global__ void router_kernel(const float* __restrict__ x,
                              const int* __restrict__ mask,
                              const float* __restrict__ rw) {
    __shared__ float rws[E_NUM * D_DIM];
    for (int i = threadIdx.x; i < E_NUM * D_DIM; i += blockDim.x) {
        int d = i >> 3, e = i & 7;
        rws[e * D_DIM + d] = rw[i];
    }
    __syncthreads();

    int wid  = blockIdx.x * (blockDim.x >> 5) + (threadIdx.x >> 5);
    int lane = threadIdx.x & 31;
    if (wid >= T_TOK) return;

    const float* xp = x + (size_t)wid * D_DIM;
    float xr[32];
#pragma unroll
    for (int j = 0; j < 32; j++) xr[j] = xp[lane + 32 * j];

    // fused convert_x: emit this token row as fp16
    __half* xo = g_x16 + (size_t)wid * D_DIM;
#pragma unroll
    for (int j = 0; j < 32; j++) xo[lane + 32 * j] = __float2half(xr[j]);

    float lg[E_NUM];
#pragma unroll
    for (int e = 0; e < E_NUM; e++) {
        float acc = 0.f;
#pragma unroll
        for (int j = 0; j < 32; j++)
            acc = fmaf(xr[j], rws[e * D_DIM + lane + 32 * j], acc);
#pragma unroll
        for (int o = 16; o; o >>= 1) acc += __shfl_xor_sync(0xffffffffu, acc, o);
        lg[e] = acc;
    }

    if (lane == 0) {
        int i0 = 0; float v0 = lg[0];
#pragma unroll
        for (int e = 1; e < E_NUM; e++) if (lg[e] > v0) { v0 = lg[e]; i0 = e; }
        int i1 = -1; float v1 = -3.0e38f;
#pragma unroll
        for (int e = 0; e < E_NUM; e++)
            if (e != i0 && lg[e] > v1) { v1 = lg[e]; i1 = e; }
        float r = expf(v1 - v0);
        float s = 1.f + r;
        g_top_i[2 * wid] = i0;  g_top_i[2 * wid + 1] = i1;
        g_top_w[2 * wid] = 1.f / s;  g_top_w[2 * wid + 1] = r / s;
        if (mask[wid] != 0) {
            atomicAdd(&g_counts[i0], 1);
            atomicAdd(&g_counts[i1], 1);
        }
    }
}

// offsets + persistent-GEMM tile list
__global__ void offsets_kernel() {
    if (threadIdx.x == 0) {
        int s = 0, nt = 0;
        for (int e = 0; e < E_NUM; e++) {
            g_offsets[e] = s;
            int n_e = g_counts[e];
            for (int r0 = 0; r0 < n_e; r0 += BM)
                g_tiles[nt++] = (e << 16) | (r0 >> 7);
            s += n_e;
        }
        g_ntiles = nt;
    }
}

__global__ void scatter_kernel(const int* __restrict__ mask) {
    int t = blockIdx.x * blockDim.x + threadIdx.x;
    if (t >= T_TOK || mask[t] == 0) return;
#pragma unroll
    for (int k = 0; k < 2; k++) {
        int e   = g_top_i[2 * t + k];
        int pos = atomicAdd(&g_cursor[e], 1);
        int idx = g_offsets[e] + pos;
        g_rows_token[idx]  = t;
        g_tok2row[2 * t + k] = idx;
    }
}

// ---------------- fused weight transpose to fp16 (homogeneous blocks) --------
// [E][K][N] fp32 -> [E][N][K] fp16 for both w1 and w2 in one launch
#define W1_BLKS ((F_DIM / 32) * (D_DIM / 32) * E_NUM)   // 16384
#define W2_BLKS ((D_DIM / 32) * (F_DIM / 32) * E_NUM)   // 16384
__global__ void convert_w(const float* __restrict__ w1,
                          const float* __restrict__ w2) {
    __shared__ float t[32][33];
    int b = blockIdx.x;
    const float* in;
    __half* o16;
    int K, N, bx, by, bz;
    if (b < W1_BLKS) {
        in = w1; o16 = g_w1t; K = D_DIM; N = F_DIM;
        bx = b & 63; by = (b >> 6) & 31; bz = b >> 11;
    } else {
        b -= W1_BLKS;
        in = w2; o16 = g_w2t; K = F_DIM; N = D_DIM;
        bx = b & 31; by = (b >> 5) & 63; bz = b >> 11;
    }
    int k0 = by * 32, n0 = bx * 32;
    size_t eb = (size_t)bz * K * N;
    const float* p = in + eb + (size_t)k0 * N + n0;
#pragma unroll
    for (int i = 0; i < 4; i++)
        t[threadIdx.y + 8 * i][threadIdx.x] =
            p[(size_t)(threadIdx.y + 8 * i) * N + threadIdx.x];
    __syncthreads();
#pragma unroll
    for (int i = 0; i < 4; i++) {
        int n = n0 + threadIdx.y + 8 * i;
        float v = t[threadIdx.x][threadIdx.y + 8 * i];
        o16[eb + (size_t)n * K + k0 + threadIdx.x] = __float2half(v);
    }
}

// ---------------- persistent grouped GEMM: fp16 HMMA, fp32 accum -------------
// G1: H[r,:] = relu(x[tok(r),:] @ w1[e] + b1[e])      K=1024, N=2048
// G2: Y[r,:] = H[r,:] @ w2[e] + b2[e]                 K=2048, N=1024
template <bool G1>
__global__ __launch_bounds__(256, 2)
void gemm_kernel(const float* __restrict__ bias) {
    constexpr int KTOT = G1 ? D_DIM : F_DIM;
    constexpr int NTOT = G1 ? F_DIM : D_DIM;
    constexpr int NCH  = KTOT / BK;
    constexpr int NX   = NTOT / BN;

    extern __shared__ __align__(1024) char smem[];
    const uint32_t sb = smem_u32(smem);
    int* tok_s  = (int*)smem;                // [0,512)
    int* tick_s = (int*)(smem + 512);        // [512,516)
    const int BUF0 = 1024;                   // 2 stages x (A 16K | B 16K)

    int tid = threadIdx.x, w = tid >> 5, lane = tid & 31;
    int wm = w >> 2, wn = w & 3;             // 2x4 warps, warp tile 64m x 32n
    int lrow = tid >> 1, lhalf = tid & 1;    // load geometry: 2 threads/row

    // ldmatrix lane-address components (validated R3-R13 geometry)
    int aR = (lane & 7) + ((lane >> 3) & 1) * 8;
    int aC = lane >> 4;
    int bRw = (lane & 7) + (lane >> 4) * 8;
    int bC = (lane >> 3) & 1;

    int g2 = lane >> 2, t4 = lane & 3;

    while (true) {
        if (tid == 0) *tick_s = atomicAdd(&g_ticket[G1 ? 0 : 1], 1);
        __syncthreads();
        int t = *tick_s;
        int ntiles = g_ntiles;
        if (t >= ntiles * NX) break;

        int nx = t % NX, ry = t / NX;
        int packed = g_tiles[ry];
        int e    = packed >> 16;
        int row0 = (packed & 0xffff) << 7;
        int n_e  = g_counts[e];
        int base = g_offsets[e];
        int n0   = nx * BN;

        if (G1 && tid < BM) {
            int r = row0 + tid;
            tok_s[tid] = (r < n_e) ? g_rows_token[base + r] : -1;
        }
        __syncthreads();

        const __half* Bw = G1 ? (g_w1t + ((size_t)e * F_DIM + n0) * D_DIM)
                              : (g_w2t + ((size_t)e * D_DIM + n0) * F_DIM);

        const __half* aP;
        int azf = 16;
        if constexpr (G1) {
            int tk = tok_s[lrow];
            if (tk >= 0) {
                aP = g_x16 + (size_t)tk * D_DIM;
            } else {
                aP = g_x16; azf = 0;         // zero-fill
            }
        } else {
            int rr = row0 + lrow; if (rr >= n_e) rr = n_e - 1;
            aP = g_H16 + (size_t)(base + rr) * F_DIM;
        }
        const __half* bP = Bw + (size_t)lrow * KTOT;

        auto issue = [&](int c) {
            int k0 = c * BK;
            uint32_t dA = sb + BUF0 + (c & 1) * STAGE_BYTES;
            uint32_t dB = dA + 16384;
#pragma unroll
            for (int s = 0; s < 4; s++) {
                int cb = (lhalf * 4 + s) * 16;           // byte within 128B row
                uint32_t doff = SWZ128(lrow * 128 + cb);
                cp16(dA + doff, (const char*)(aP + k0) + cb, azf);
                cp16(dB + doff, (const char*)(bP + k0) + cb, 16);
            }
            cp_commit();
        };

        float acc[4][4][4];
#pragma unroll
        for (int i = 0; i < 4; i++)
#pragma unroll
            for (int j = 0; j < 4; j++)
#pragma unroll
                for (int q = 0; q < 4; q++) acc[i][j][q] = 0.f;

        issue(0);
        issue(1);

        for (int c = 0; c < NCH; c++) {
            cp_wait1();                      // drains any stale empty groups too
            __syncthreads();

            uint32_t bufA = sb + BUF0 + (c & 1) * STAGE_BYTES;
            uint32_t bufB = bufA + 16384;
#pragma unroll
            for (int ks = 0; ks < 4; ks++) {
                uint32_t fB[4][2], tmp[4];
#pragma unroll
                for (int pp = 0; pp < 2; pp++) {
                    int off = (wn * 32 + pp * 16 + bRw) * 128 + (ks * 2 + bC) * 16;
                    ldsm4(tmp, bufB + SWZ128(off));
                    fB[pp * 2][0] = tmp[0]; fB[pp * 2][1] = tmp[1];
                    fB[pp * 2 + 1][0] = tmp[2]; fB[pp * 2 + 1][1] = tmp[3];
                }
                uint32_t fA[4][4];
#pragma unroll
                for (int mf = 0; mf < 4; mf++) {
                    int off = (wm * 64 + mf * 16 + aR) * 128 + (ks * 2 + aC) * 16;
                    ldsm4(fA[mf], bufA + SWZ128(off));
                }
#pragma unroll
                for (int mf = 0; mf < 4; mf++)
#pragma unroll
                    for (int nf = 0; nf < 4; nf++)
                        hmma(acc[mf][nf], fA[mf], fB[nf]);
            }
            __syncthreads();
            if (c + 2 < NCH) issue(c + 2);
            else cp_commit();                // keep group accounting uniform
        }

        // ---------------- epilogue ----------------
        float bia[4][2];
#pragma unroll
        for (int nf = 0; nf < 4; nf++) {
#pragma unroll
            for (int j = 0; j < 2; j++)
                bia[nf][j] =
                    bias[(size_t)e * NTOT + n0 + wn * 32 + nf * 8 + t4 * 2 + j];
        }

#pragma unroll
        for (int mf = 0; mf < 4; mf++) {
#pragma unroll
            for (int half = 0; half < 2; half++) {
                int r = row0 + wm * 64 + mf * 16 + g2 + half * 8;
                if (r >= n_e) continue;
                if constexpr (G1) {
                    size_t ro = (size_t)(base + r) * F_DIM;
#pragma unroll
                    for (int nf = 0; nf < 4; nf++) {
                        int col = n0 + wn * 32 + nf * 8 + t4 * 2;
                        float v0 = fmaxf(acc[mf][nf][2 * half + 0] + bia[nf][0], 0.f);
                        float v1 = fmaxf(acc[mf][nf][2 * half + 1] + bia[nf][1], 0.f);
                        *(__half2*)(g_H16 + ro + col) =
                            __halves2half2(__float2half(v0), __float2half(v1));
                    }
                } else {
                    size_t ro = (size_t)(base + r) * D_DIM;
#pragma unroll
                    for (int nf = 0; nf < 4; nf++) {
                        int col = n0 + wn * 32 + nf * 8 + t4 * 2;
                        float v0 = acc[mf][nf][2 * half + 0] + bia[nf][0];
                        float v1 = acc[mf][nf][2 * half + 1] + bia[nf][1];
                        *(__half2*)(g_Y16 + ro + col) =
                            __halves2half2(__float2half(v0), __float2half(v1));
                    }
                }
            }
        }
        __syncthreads();   // protect tick_s / smem buffers before next tile
    }
}

// ---------------- combine: out[t] = w0*Y[row0] + w1*Y[row1] ------------------
__global__ void combine_kernel(const int* __restrict__ mask,
                               float* __restrict__ out) {
    int t  = blockIdx.x;
    int c8 = threadIdx.x * 8;                // 128 threads x 8 halfs
    float o[8];
#pragma unroll
    for (int j = 0; j < 8; j++) o[j] = 0.f;
    if (mask[t] != 0) {
        int   r0 = g_tok2row[2 * t],     r1 = g_tok2row[2 * t + 1];
        float w0 = g_top_w[2 * t],       w1 = g_top_w[2 * t + 1];
        uint4 ya = *(const uint4*)(g_Y16 + (size_t)r0 * D_DIM + c8);
        uint4 yb = *(const uint4*)(g_Y16 + (size_t)r1 * D_DIM + c8);
        const __half2* pa = (const __half2*)&ya;
        const __half2* pb = (const __half2*)&yb;
#pragma unroll
        for (int j = 0; j < 4; j++) {
            float2 a = __half22float2(pa[j]);
            float2 b = __half22float2(pb[j]);
            o[2 * j + 0] = w0 * a.x + w1 * b.x;
            o[2 * j + 1] = w0 * a.y + w1 * b.y;
        }
    }
    *(float4*)(out + (size_t)t * D_DIM + c8)     = make_float4(o[0], o[1], o[2], o[3]);
    *(float4*)(out + (size_t)t * D_DIM + c8 + 4) = make_float4(o[4], o[5], o[6], o[7]);
}

// ---------------- launch -----------------------------------------------------
extern "C" void kernel_launch(void* const* d_in, const int* in_sizes, int n_in,
                              void* d_out, int out_size) {
    const float* x    = (const float*)d_in[0];
    const int*   mask = (const int*)d_in[1];
    const float* rw   = (const float*)d_in[2];
    const float* w1   = (const float*)d_in[3];
    const float* b1   = (const float*)d_in[4];
    const float* w2   = (const float*)d_in[5];
    const float* b2   = (const float*)d_in[6];
    float*       out  = (float*)d_out;

    cudaFuncSetAttribute(gemm_kernel<true>,
                         cudaFuncAttributeMaxDynamicSharedMemorySize, SMEM_SZ);
    cudaFuncSetAttribute(gemm_kernel<false>,
                         cudaFuncAttributeMaxDynamicSharedMemorySize, SMEM_SZ);

    init_kernel<<<1, 32>>>();
    convert_w<<<W1_BLKS + W2_BLKS, dim3(32, 8)>>>(w1, w2);
    router_kernel<<<T_TOK / 8, 256>>>(x, mask, rw);
    offsets_kernel<<<1, 32>>>();
    scatter_kernel<<<(T_TOK + 255) / 256, 256>>>(mask);

    gemm_kernel<true><<<GEMM_CTAS, 256, SMEM_SZ>>>(b1);
    gemm_kernel<false><<<GEMM_CTAS, 256, SMEM_SZ>>>(b2);

    combine_kernel<<<T_TOK, 128>>>(mask, out);
}

// round 16
// speedup vs baseline: 1.0225x; 1.0225x over previous
#include <cuda_runtime.h>
#include <cuda_fp16.h>
#include <cstdint>

// Problem constants (B=4, S=2048, D=1024, E=8, F=2048, top_k=2)
#define T_TOK 8192
#define D_DIM 1024
#define E_NUM 8
#define F_DIM 2048
#define RMAX  (2 * T_TOK)

#define BM 128
#define BN 128
#define BK 64                         // 64 fp16 k-values = 128B rows
#define STAGE_BYTES (2 * 16384)       // A | B, 16KB each
#define SMEM_SZ (1024 + 2 * STAGE_BYTES)   // 2-stage -> 65KB, 2 CTAs/SM

// ---------------- device scratch (no allocation allowed) --------------------
__device__ __half g_x16[(size_t)T_TOK * D_DIM];                // x fp16
__device__ __half g_H16[(size_t)RMAX * F_DIM];                 // H fp16
__device__ __half g_Y16[(size_t)RMAX * D_DIM];                 // expert outputs fp16
__device__ __half g_w1t[(size_t)E_NUM * F_DIM * D_DIM];        // [E][F][D] fp16
__device__ __half g_w2t[(size_t)E_NUM * D_DIM * F_DIM];        // [E][D][F] fp16
__device__ int   g_rows_token[RMAX];
__device__ int   g_tok2row[2 * T_TOK];
__device__ int   g_top_i[2 * T_TOK];
__device__ float g_top_w[2 * T_TOK];
__device__ int   g_counts[E_NUM];
__device__ int   g_offsets[E_NUM];
__device__ int   g_cursor[E_NUM];

// ---------------- helpers ----------------------------------------------------
__device__ __forceinline__ uint32_t smem_u32(const void* p) {
    uint32_t a;
    asm("{ .reg .u64 t; cvta.to.shared.u64 t, %1; cvt.u32.u64 %0, t; }"
        : "=r"(a) : "l"(p));
    return a;
}
// standard 128B-row swizzle (Swizzle<3,4,3>): 16B-col bits[6:4] ^= row bits[9:7]
#define SWZ128(o) ((o) ^ (((o) >> 3) & 0x70))

__device__ __forceinline__ void ldsm4(uint32_t* r, uint32_t addr) {
    asm volatile("ldmatrix.sync.aligned.m8n8.x4.shared.b16 {%0,%1,%2,%3}, [%4];"
                 : "=r"(r[0]), "=r"(r[1]), "=r"(r[2]), "=r"(r[3]) : "r"(addr));
}
__device__ __forceinline__ void hmma(float* c, const uint32_t* a,
                                     const uint32_t* b) {
    asm volatile(
        "mma.sync.aligned.m16n8k16.row.col.f32.f16.f16.f32 "
        "{%0,%1,%2,%3}, {%4,%5,%6,%7}, {%8,%9}, {%0,%1,%2,%3};"
        : "+f"(c[0]), "+f"(c[1]), "+f"(c[2]), "+f"(c[3])
        : "r"(a[0]), "r"(a[1]), "r"(a[2]), "r"(a[3]), "r"(b[0]), "r"(b[1]));
}
__device__ __forceinline__ void cp16(uint32_t dst, const void* src, int nbytes) {
    asm volatile("cp.async.cg.shared.global [%0], [%1], 16, %2;"
                 :: "r"(dst), "l"(src), "r"(nbytes) : "memory");
}
__device__ __forceinline__ void cp_commit() {
    asm volatile("cp.async.commit_group;" ::: "memory");
}
__device__ __forceinline__ void cp_wait1() {
    asm volatile("cp.async.wait_group 1;" ::: "memory");
}

// ---------------- init ------------------------------------------------------
__global__ void init_kernel() {
    int i = threadIdx.x;
    if (i < E_NUM) { g_counts[i] = 0; g_cursor[i] = 0; }
}

// ---------------- router (+ fused x -> fp16 emit) ----------------------------
__global__ void router_kernel(const float* __restrict__ x,
                              const int* __restrict__ mask,
                              const float* __restrict__ rw) {
    __shared__ float rws[E_NUM * D_DIM];
    for (int i = threadIdx.x; i < E_NUM * D_DIM; i += blockDim.x) {
        int d = i >> 3, e = i & 7;
        rws[e * D_DIM + d] = rw[i];
    }
    __syncthreads();

    int wid  = blockIdx.x * (blockDim.x >> 5) + (threadIdx.x >> 5);
    int lane = threadIdx.x & 31;
    if (wid >= T_TOK) return;

    const float* xp = x + (size_t)wid * D_DIM;
    float xr[32];
#pragma unroll
    for (int j = 0; j < 32; j++) xr[j] = xp[lane + 32 * j];

    // fused convert_x: emit this token row as fp16
    __half* xo = g_x16 + (size_t)wid * D_DIM;
#pragma unroll
    for (int j = 0; j < 32; j++) xo[lane + 32 * j] = __float2half(xr[j]);

    float lg[E_NUM];
#pragma unroll
    for (int e = 0; e < E_NUM; e++) {
        float acc = 0.f;
#pragma unroll
        for (int j = 0; j < 32; j++)
            acc = fmaf(xr[j], rws[e * D_DIM + lane + 32 * j], acc);
#pragma unroll
        for (int o = 16; o; o >>= 1) acc += __shfl_xor_sync(0xffffffffu, acc, o);
        lg[e] = acc;
    }

    if (lane == 0) {
        int i0 = 0; float v0 = lg[0];
#pragma unroll
        for (int e = 1; e < E_NUM; e++) if (lg[e] > v0) { v0 = lg[e]; i0 = e; }
        int i1 = -1; float v1 = -3.0e38f;
#pragma unroll
        for (int e = 0; e < E_NUM; e++)
            if (e != i0 && lg[e] > v1) { v1 = lg[e]; i1 = e; }
        float r = expf(v1 - v0);
        float s = 1.f + r;
        g_top_i[2 * wid] = i0;  g_top_i[2 * wid + 1] = i1;
        g_top_w[2 * wid] = 1.f / s;  g_top_w[2 * wid + 1] = r / s;
        if (mask[wid] != 0) {
            atomicAdd(&g_counts[i0], 1);
            atomicAdd(&g_counts[i1], 1);
        }
    }
}

__global__ void offsets_kernel() {
    if (threadIdx.x == 0) {
        int s = 0;
        for (int e = 0; e < E_NUM; e++) { g_offsets[e] = s; s += g_counts[e]; }
    }
}

__global__ void scatter_kernel(const int* __restrict__ mask) {
    int t = blockIdx.x * blockDim.x + threadIdx.x;
    if (t >= T_TOK || mask[t] == 0) return;
#pragma unroll
    for (int k = 0; k < 2; k++) {
        int e   = g_top_i[2 * t + k];
        int pos = atomicAdd(&g_cursor[e], 1);
        int idx = g_offsets[e] + pos;
        g_rows_token[idx]  = t;
        g_tok2row[2 * t + k] = idx;
    }
}

// ---------------- fused weight transpose to fp16 (wide-store version) --------
// [E][K][N] fp32 -> [E][N][K] fp16; 64k x 32n tiles, 256 threads.
// Loads: 128B/warp rows.  Stores: half2/lane -> 128B/warp columns.
#define WC_BLKS1 (E_NUM * (F_DIM / 32) * (D_DIM / 64))   // 8192
#define WC_BLKS2 (E_NUM * (D_DIM / 32) * (F_DIM / 64))   // 8192
__global__ __launch_bounds__(256)
void convert_w(const float* __restrict__ w1, const float* __restrict__ w2) {
    __shared__ float t[64][33];
    int b = blockIdx.x;
    const float* in;
    __half* o16;
    int K, N;
    if (b < WC_BLKS1) { in = w1; o16 = g_w1t; K = D_DIM; N = F_DIM; }
    else { b -= WC_BLKS1; in = w2; o16 = g_w2t; K = F_DIM; N = D_DIM; }
    int nb = N / 32, kb = K / 64;
    int bx = b % nb;                 // n tile
    int by = (b / nb) % kb;          // k tile
    int bz = b / (nb * kb);          // expert
    int n0 = bx * 32, k0 = by * 64;
    size_t eb = (size_t)bz * K * N;
    int lane = threadIdx.x & 31, wrp = threadIdx.x >> 5;

    const float* p = in + eb + (size_t)k0 * N + n0;
#pragma unroll
    for (int i = 0; i < 8; i++) {
        int k = wrp * 8 + i;
        t[k][lane] = p[(size_t)k * N + lane];
    }
    __syncthreads();
#pragma unroll
    for (int i = 0; i < 4; i++) {
        int n = wrp * 4 + i;
        __half2 h = __halves2half2(__float2half(t[2 * lane][n]),
                                   __float2half(t[2 * lane + 1][n]));
        *(__half2*)(o16 + eb + (size_t)(n0 + n) * K + k0 + 2 * lane) = h;
    }
}

// ---------------- grouped GEMM: plain fp16 HMMA, fp32 accum ------------------
// G1: H[r,:] = relu(x[tok(r),:] @ w1[e] + b1[e])      K=1024, N=2048
// G2: Y[r,:] = H[r,:] @ w2[e] + b2[e]                 K=2048, N=1024
template <bool G1>
__global__ __launch_bounds__(256, 2)
void gemm_kernel(const float* __restrict__ bias) {
    constexpr int KTOT = G1 ? D_DIM : F_DIM;
    constexpr int NTOT = G1 ? F_DIM : D_DIM;
    constexpr int NCH  = KTOT / BK;

    extern __shared__ __align__(1024) char smem[];
    const uint32_t sb = smem_u32(smem);
    int* tok_s = (int*)smem;                 // [0,512)
    const int BUF0 = 1024;                   // 2 stages x (A 16K | B 16K)

    int e    = blockIdx.z;
    int n_e  = g_counts[e];
    int row0 = blockIdx.y * BM;
    if (row0 >= n_e) return;
    int base = g_offsets[e];
    int n0   = blockIdx.x * BN;

    int tid = threadIdx.x, w = tid >> 5, lane = tid & 31;
    int wm = w >> 2, wn = w & 3;             // 2x4 warps, warp tile 64m x 32n

    if (G1 && tid < BM) {
        int r = row0 + tid;
        tok_s[tid] = (r < n_e) ? g_rows_token[base + r] : -1;
    }
    __syncthreads();

    const __half* Bw = G1 ? (g_w1t + ((size_t)e * F_DIM + n0) * D_DIM)
                          : (g_w2t + ((size_t)e * D_DIM + n0) * F_DIM);

    // load geometry: 2 threads per row; each thread 4x16B per matrix
    int lrow = tid >> 1, lhalf = tid & 1;

    const __half* aP;
    int azf = 16;
    if constexpr (G1) {
        int tk = tok_s[lrow];
        if (tk >= 0) {
            aP = g_x16 + (size_t)tk * D_DIM;
        } else {
            aP = g_x16; azf = 0;             // zero-fill
        }
    } else {
        int rr = row0 + lrow; if (rr >= n_e) rr = n_e - 1;
        aP = g_H16 + (size_t)(base + rr) * F_DIM;
    }
    const __half* bP = Bw + (size_t)lrow * KTOT;

    auto issue = [&](int c) {
        int k0 = c * BK;
        uint32_t dA = sb + BUF0 + (c & 1) * STAGE_BYTES;
        uint32_t dB = dA + 16384;
#pragma unroll
        for (int s = 0; s < 4; s++) {
            int cb = (lhalf * 4 + s) * 16;               // byte within 128B row
            uint32_t doff = SWZ128(lrow * 128 + cb);
            cp16(dA + doff, (const char*)(aP + k0) + cb, azf);
            cp16(dB + doff, (const char*)(bP + k0) + cb, 16);
        }
        cp_commit();
    };

    float acc[4][4][4];
#pragma unroll
    for (int i = 0; i < 4; i++)
#pragma unroll
        for (int j = 0; j < 4; j++)
#pragma unroll
            for (int q = 0; q < 4; q++) acc[i][j][q] = 0.f;

    // ldmatrix lane-address components (validated R3-R13 geometry)
    int aR = (lane & 7) + ((lane >> 3) & 1) * 8;
    int aC = lane >> 4;
    int bRw = (lane & 7) + (lane >> 4) * 8;
    int bC = (lane >> 3) & 1;

    issue(0);
    issue(1);

    for (int c = 0; c < NCH; c++) {
        cp_wait1();
        __syncthreads();

        uint32_t bufA = sb + BUF0 + (c & 1) * STAGE_BYTES;
        uint32_t bufB = bufA + 16384;
#pragma unroll
        for (int ks = 0; ks < 4; ks++) {
            uint32_t fB[4][2], tmp[4];
#pragma unroll
            for (int pp = 0; pp < 2; pp++) {
                int off = (wn * 32 + pp * 16 + bRw) * 128 + (ks * 2 + bC) * 16;
                ldsm4(tmp, bufB + SWZ128(off));
                fB[pp * 2][0] = tmp[0]; fB[pp * 2][1] = tmp[1];
                fB[pp * 2 + 1][0] = tmp[2]; fB[pp * 2 + 1][1] = tmp[3];
            }
            uint32_t fA[4][4];
#pragma unroll
            for (int mf = 0; mf < 4; mf++) {
                int off = (wm * 64 + mf * 16 + aR) * 128 + (ks * 2 + aC) * 16;
                ldsm4(fA[mf], bufA + SWZ128(off));
            }
#pragma unroll
            for (int mf = 0; mf < 4; mf++)
#pragma unroll
                for (int nf = 0; nf < 4; nf++)
                    hmma(acc[mf][nf], fA[mf], fB[nf]);
        }
        __syncthreads();
        if (c + 2 < NCH) issue(c + 2);
        else cp_commit();                    // keep group accounting uniform
    }

    // ---------------- epilogue ----------------
    int g = lane >> 2, t4 = lane & 3;
    float bia[4][2];
#pragma unroll
    for (int nf = 0; nf < 4; nf++) {
#pragma unroll
        for (int j = 0; j < 2; j++)
            bia[nf][j] = bias[(size_t)e * NTOT + n0 + wn * 32 + nf * 8 + t4 * 2 + j];
    }

#pragma unroll
    for (int mf = 0; mf < 4; mf++) {
#pragma unroll
        for (int half = 0; half < 2; half++) {
            int r = row0 + wm * 64 + mf * 16 + g + half * 8;
            if (r >= n_e) continue;
            if constexpr (G1) {
                size_t ro = (size_t)(base + r) * F_DIM;
#pragma unroll
                for (int nf = 0; nf < 4; nf++) {
                    int col = n0 + wn * 32 + nf * 8 + t4 * 2;
                    float v0 = fmaxf(acc[mf][nf][2 * half + 0] + bia[nf][0], 0.f);
                    float v1 = fmaxf(acc[mf][nf][2 * half + 1] + bia[nf][1], 0.f);
                    *(__half2*)(g_H16 + ro + col) =
                        __halves2half2(__float2half(v0), __float2half(v1));
                }
            } else {
                size_t ro = (size_t)(base + r) * D_DIM;
#pragma unroll
                for (int nf = 0; nf < 4; nf++) {
                    int col = n0 + wn * 32 + nf * 8 + t4 * 2;
                    float v0 = acc[mf][nf][2 * half + 0] + bia[nf][0];
                    float v1 = acc[mf][nf][2 * half + 1] + bia[nf][1];
                    *(__half2*)(g_Y16 + ro + col) =
                        __halves2half2(__float2half(v0), __float2half(v1));
                }
            }
        }
    }
}

// ---------------- combine: out[t] = w0*Y[row0] + w1*Y[row1] ------------------
__global__ void combine_kernel(const int* __restrict__ mask,
                               float* __restrict__ out) {
    int t  = blockIdx.x;
    int c8 = threadIdx.x * 8;                // 128 threads x 8 halfs
    float o[8];
#pragma unroll
    for (int j = 0; j < 8; j++) o[j] = 0.f;
    if (mask[t] != 0) {
        int   r0 = g_tok2row[2 * t],     r1 = g_tok2row[2 * t + 1];
        float w0 = g_top_w[2 * t],       w1 = g_top_w[2 * t + 1];
        uint4 ya = *(const uint4*)(g_Y16 + (size_t)r0 * D_DIM + c8);
        uint4 yb = *(const uint4*)(g_Y16 + (size_t)r1 * D_DIM + c8);
        const __half2* pa = (const __half2*)&ya;
        const __half2* pb = (const __half2*)&yb;
#pragma unroll
        for (int j = 0; j < 4; j++) {
            float2 a = __half22float2(pa[j]);
            float2 b = __half22float2(pb[j]);
            o[2 * j + 0] = w0 * a.x + w1 * b.x;
            o[2 * j + 1] = w0 * a.y + w1 * b.y;
        }
    }
    *(float4*)(out + (size_t)t * D_DIM + c8)     = make_float4(o[0], o[1], o[2], o[3]);
    *(float4*)(out + (size_t)t * D_DIM + c8 + 4) = make_float4(o[4], o[5], o[6], o[7]);
}

// ---------------- launch -----------------------------------------------------
extern "C" void kernel_launch(void* const* d_in, const int* in_sizes, int n_in,
                              void* d_out, int out_size) {
    const float* x    = (const float*)d_in[0];
    const int*   mask = (const int*)d_in[1];
    const float* rw   = (const float*)d_in[2];
    const float* w1   = (const float*)d_in[3];
    const float* b1   = (const float*)d_in[4];
    const float* w2   = (const float*)d_in[5];
    const float* b2   = (const float*)d_in[6];
    float*       out  = (float*)d_out;

    cudaFuncSetAttribute(gemm_kernel<true>,
                         cudaFuncAttributeMaxDynamicSharedMemorySize, SMEM_SZ);
    cudaFuncSetAttribute(gemm_kernel<false>,
                         cudaFuncAttributeMaxDynamicSharedMemorySize, SMEM_SZ);

    init_kernel<<<1, 32>>>();
    convert_w<<<WC_BLKS1 + WC_BLKS2, 256>>>(w1, w2);
    router_kernel<<<T_TOK / 8, 256>>>(x, mask, rw);
    offsets_kernel<<<1, 32>>>();
    scatter_kernel<<<(T_TOK + 255) / 256, 256>>>(mask);

    dim3 g1(F_DIM / BN, RMAX / BM, E_NUM);
    gemm_kernel<true><<<g1, 256, SMEM_SZ>>>(b1);
    dim3 g2(D_DIM / BN, RMAX / BM, E_NUM);
    gemm_kernel<false><<<g2, 256, SMEM_SZ>>>(b2);

    combine_kernel<<<T_TOK, 128>>>(mask, out);
}